// round 15
// baseline (speedup 1.0000x reference)
#include <cuda_runtime.h>
#include <cuda_fp16.h>

#define Hh 250
#define Ww 400
#define N_RAYS (Hh*Ww)            // 100000
#define N_SAMPLES 1000000
#define P_CNT 50000
#define STEP_SIZE 0.005f
#define PBLK 384                  // C*3*DIM elems per p
#define PPAD 416                  // 16 rows of 24 floats padded to 26

// Scratch (static device allocations are permitted)
__device__ __half  g_trivecsH[(size_t)P_CNT * PBLK];  // (P,3,DIM,C) half, ~38.4MB
__device__ __half  g_dc[(size_t)P_CNT * 64];          // per p: 16 dens + 48 colors halves (128B)
__device__ float4  g_samp[N_SAMPLES];                 // {alpha, r, g, b}
__device__ int     g_start[N_RAYS];
__device__ int     g_end[N_RAYS];

// ---------------------------------------------------------------------------
// Kernel 1: transpose trivecs (P,C,3,DIM) fp32 -> (P,3,DIM,C) fp16.
// Two 4-p groups per 384-thread block. Folds in dens+colors fp16 pack and
// segment-table zeroing.
// ---------------------------------------------------------------------------
__global__ __launch_bounds__(384) void transpose_k(const float4* __restrict__ in,
                                                   const float4* __restrict__ densities4,
                                                   const float4* __restrict__ colors4) {
    __shared__ float sm[8 * PPAD];
    int t = threadIdx.x;
    int gid = blockIdx.x * 384 + t;            // up to 2.4M
    size_t base4 = (size_t)blockIdx.x * 768;   // float4 index of first 4-p group

    float4 v0 = __ldcs(in + base4 + t);
    float4 v1 = __ldcs(in + base4 + 384 + t);

    // folded init of segment tables
    if (gid < N_RAYS) { g_start[gid] = 0; g_end[gid] = 0; }
    // folded densities+colors fp32 -> fp16 pack: per-p block = 64 halves
    // [0:16) = densities, [16:64) = colors (c*3+k). Thread handles 4 floats.
    if (gid < P_CNT * 16) {
        int p = gid >> 4;
        int o = (gid & 15) * 4;                // 0,4,...,60
        float4 src = (o < 16)
            ? __ldcs(densities4 + ((size_t)p * 16 + o) / 4)
            : __ldcs(colors4    + ((size_t)p * 48 + (o - 16)) / 4);
        union { __half2 h[2]; uint2 u; } cv;
        cv.h[0] = __floats2half2_rn(src.x, src.y);
        cv.h[1] = __floats2half2_rn(src.z, src.w);
        reinterpret_cast<uint2*>(g_dc)[(size_t)p * 16 + (o >> 2)] = cv.u;
    }

    int m  = t * 4;                 // float offset within a 4-p group
    int pl = t / 96;                // local p (96 float4 per p)
    int mo = m - pl * PBLK;         // 0..383: row = mo/24 (c), col = mo%24 (a*8+d)
    int pi = mo + 2 * (mo / 24);    // padded index
    float* s0 = sm + pl * PPAD;
    float* s1 = sm + (4 + pl) * PPAD;
    s0[pi + 0] = v0.x; s0[pi + 1] = v0.y; s0[pi + 2] = v0.z; s0[pi + 3] = v0.w;
    s1[pi + 0] = v1.x; s1[pi + 1] = v1.y; s1[pi + 2] = v1.z; s1[pi + 3] = v1.w;
    __syncthreads();

    int c = mo & 15, d = (mo >> 4) & 7, a = mo >> 7;
    int i0 = c * 26 + a * 8 + d;
    const float* r0 = sm + pl * PPAD;
    const float* r1 = sm + (4 + pl) * PPAD;
    union { __half2 h[2]; uint2 u; } o0, o1;
    o0.h[0] = __floats2half2_rn(r0[i0],      r0[i0 + 26]);
    o0.h[1] = __floats2half2_rn(r0[i0 + 52], r0[i0 + 78]);
    o1.h[0] = __floats2half2_rn(r1[i0],      r1[i0 + 26]);
    o1.h[1] = __floats2half2_rn(r1[i0 + 52], r1[i0 + 78]);
    int oidx = pl * 96 + a * 32 + d * 4 + (c >> 2);
    uint2* outp = reinterpret_cast<uint2*>(g_trivecsH);
    outp[base4 + oidx]       = o0.u;
    outp[base4 + 384 + oidx] = o1.u;
}

// ---------------------------------------------------------------------------
// Kernel 2: per-sample feature/sigma/color (+ segment boundaries).
// 2 threads per sample, 8 channels each via 16B gathers; pair shuffle-reduce.
// ---------------------------------------------------------------------------
__global__ __launch_bounds__(256) void sample_k(
    const float* __restrict__ gws,         // (N, 3)
    const float* __restrict__ gwl,         // (N, 3)
    const int*   __restrict__ gis,         // (N, 3)
    const int*   __restrict__ gil,         // (N, 3)
    const int*   __restrict__ tfid,        // (N,)
    const int*   __restrict__ ray_id)      // (N,) sorted
{
    int t = blockIdx.x * blockDim.x + threadIdx.x;
    int n = t >> 1;
    if (n >= N_SAMPLES) return;
    int q = t & 1;

    int p = __ldcs(tfid + n);
    const __half* base = g_trivecsH + (size_t)p * PBLK + q * 8;

    float f[8];
    #pragma unroll
    for (int i = 0; i < 8; i++) f[i] = 1.f;

    #pragma unroll
    for (int a = 0; a < 3; a++) {
        int   is = __ldcs(gis + n * 3 + a);
        int   il = __ldcs(gil + n * 3 + a);
        float ws = __ldcs(gws + n * 3 + a);
        float wl = __ldcs(gwl + n * 3 + a);
        uint4 rs = *reinterpret_cast<const uint4*>(base + a * 128 + is * 16);
        uint4 rl = *reinterpret_cast<const uint4*>(base + a * 128 + il * 16);
        const __half2* hs = reinterpret_cast<const __half2*>(&rs);
        const __half2* hl = reinterpret_cast<const __half2*>(&rl);
        #pragma unroll
        for (int i = 0; i < 4; i++) {
            float2 vs = __half22float2(hs[i]);
            float2 vl = __half22float2(hl[i]);
            f[i * 2 + 0] *= vs.x * ws + vl.x * wl;
            f[i * 2 + 1] *= vs.y * ws + vl.y * wl;
        }
    }

    // densities: halves [q*8, q*8+8) of p's 64-half block
    const __half* dch = g_dc + (size_t)p * 64;
    uint4 du = *reinterpret_cast<const uint4*>(dch + q * 8);
    const __half2* dh = reinterpret_cast<const __half2*>(&du);
    float sig = 0.f;
    #pragma unroll
    for (int i = 0; i < 4; i++) {
        float2 dv = __half22float2(dh[i]);
        sig += f[i * 2 + 0] * dv.x + f[i * 2 + 1] * dv.y;
    }

    // colors: halves [16 + q*24, 16 + q*24 + 24); element (c_local,k) at c_local*3+k
    const __half* cbh = dch + 16 + q * 24;
    uint4 cu0 = *reinterpret_cast<const uint4*>(cbh);
    uint4 cu1 = *reinterpret_cast<const uint4*>(cbh + 8);
    uint4 cu2 = *reinterpret_cast<const uint4*>(cbh + 16);
    float col[24];
    {
        const __half2* ch = reinterpret_cast<const __half2*>(&cu0);
        #pragma unroll
        for (int i = 0; i < 4; i++) { float2 v = __half22float2(ch[i]); col[i*2] = v.x; col[i*2+1] = v.y; }
        ch = reinterpret_cast<const __half2*>(&cu1);
        #pragma unroll
        for (int i = 0; i < 4; i++) { float2 v = __half22float2(ch[i]); col[8+i*2] = v.x; col[8+i*2+1] = v.y; }
        ch = reinterpret_cast<const __half2*>(&cu2);
        #pragma unroll
        for (int i = 0; i < 4; i++) { float2 v = __half22float2(ch[i]); col[16+i*2] = v.x; col[16+i*2+1] = v.y; }
    }
    float cr = 0.f, cg = 0.f, cbv = 0.f;
    #pragma unroll
    for (int c = 0; c < 8; c++) {
        cr  += f[c] * col[c * 3 + 0];
        cg  += f[c] * col[c * 3 + 1];
        cbv += f[c] * col[c * 3 + 2];
    }

    // pair reduction
    sig += __shfl_xor_sync(0xffffffffu, sig, 1);
    cr  += __shfl_xor_sync(0xffffffffu, cr,  1);
    cg  += __shfl_xor_sync(0xffffffffu, cg,  1);
    cbv += __shfl_xor_sync(0xffffffffu, cbv, 1);

    if (q == 0) {
        // DENSITY_SHIFT = 0, DENSITY_SCALE = 1
        float density = (sig > 15.f) ? sig : log1pf(__expf(sig));
        float alpha = 1.f - __expf(-density * STEP_SIZE);
        float rr = 1.f / (1.f + __expf(-cr));
        float rg = 1.f / (1.f + __expf(-cg));
        float rb = 1.f / (1.f + __expf(-cbv));
        g_samp[n] = make_float4(alpha, rr, rg, rb);
    } else {
        // __ldg so the n-1/n/n+1 neighborhood hits L1 (not streaming-evicted)
        int r = __ldg(ray_id + n);
        int rp = (n > 0) ? __ldg(ray_id + n - 1) : -1;
        int rn = (n < N_SAMPLES - 1) ? __ldg(ray_id + n + 1) : -1;
        if (rp != r) g_start[r] = n;
        if (rn != r) g_end[r]   = n + 1;
    }
}

// ---------------------------------------------------------------------------
// Kernel 3: thread-per-ray composite; multiplicative transmittance;
// depth-2 prefetch (two independent loads in flight).
// ---------------------------------------------------------------------------
__global__ __launch_bounds__(256) void ray_k(
    const int*   __restrict__ step_id,
    const float* __restrict__ t_min,
    const float* __restrict__ bg,
    float*       __restrict__ out)
{
    int r = blockIdx.x * blockDim.x + threadIdx.x;
    if (r >= N_RAYS) return;

    int s = g_start[r];
    int e = g_end[r];
    float tm = t_min[r];

    float T = 1.f;
    float ra = 0.f, ga = 0.f, ba = 0.f, da = 0.f;

    float4 sp0, sp1; int st0 = 0, st1 = 0;
    if (s < e)     { sp0 = __ldcs(g_samp + s);     st0 = __ldcs(step_id + s); }
    if (s + 1 < e) { sp1 = __ldcs(g_samp + s + 1); st1 = __ldcs(step_id + s + 1); }

    for (int j = s; j < e; j++) {
        float4 cur = sp0;
        int    cst = st0;
        sp0 = sp1; st0 = st1;
        if (j + 2 < e) { sp1 = __ldcs(g_samp + j + 2); st1 = __ldcs(step_id + j + 2); }
        float w = cur.x * T;
        ra += w * cur.y;
        ga += w * cur.z;
        ba += w * cur.w;
        da += w * (tm + (float)cst * STEP_SIZE);
        T *= (1.f - cur.x);
    }
    out[0 * N_RAYS + r] = ra + T * __ldg(bg + 0);
    out[1 * N_RAYS + r] = ga + T * __ldg(bg + 1);
    out[2 * N_RAYS + r] = ba + T * __ldg(bg + 2);
    out[3 * N_RAYS + r] = da;          // depth map
    out[4 * N_RAYS + r] = 1.f - T;     // alpha map
}

extern "C" void kernel_launch(void* const* d_in, const int* in_sizes, int n_in,
                              void* d_out, int out_size) {
    const float* trivecs   = (const float*)d_in[0];
    const float* densities = (const float*)d_in[1];
    const float* colors    = (const float*)d_in[2];
    const float* gws       = (const float*)d_in[3];
    const float* gwl       = (const float*)d_in[4];
    const float* t_min     = (const float*)d_in[5];
    const float* bg        = (const float*)d_in[6];
    const int*   gis       = (const int*)d_in[7];
    const int*   gil       = (const int*)d_in[8];
    const int*   tfid      = (const int*)d_in[9];
    const int*   ray_id    = (const int*)d_in[10];
    const int*   step_id   = (const int*)d_in[11];
    float* out = (float*)d_out;

    transpose_k<<<P_CNT / 8, 384>>>((const float4*)trivecs,
                                    (const float4*)densities,
                                    (const float4*)colors);
    sample_k<<<(2 * N_SAMPLES + 255) / 256, 256>>>(gws, gwl, gis, gil, tfid, ray_id);
    ray_k<<<(N_RAYS + 255) / 256, 256>>>(step_id, t_min, bg, out);
}

// round 16
// speedup vs baseline: 1.4285x; 1.4285x over previous
#include <cuda_runtime.h>
#include <cuda_fp16.h>

#define Hh 250
#define Ww 400
#define N_RAYS (Hh*Ww)            // 100000
#define N_SAMPLES 1000000
#define P_CNT 50000
#define STEP_SIZE 0.005f
#define PBLK 384                  // C*3*DIM elems per p
#define PPAD 416                  // 16 rows of 24 floats padded to 26

// Scratch (static device allocations are permitted)
__device__ __half  g_trivecsH[(size_t)P_CNT * PBLK];  // (P,3,DIM,C) half, ~38.4MB
__device__ __half  g_dc[(size_t)P_CNT * 64];          // per p: 16 dens + 48 colors halves (128B)
__device__ float4  g_samp[N_SAMPLES];                 // {alpha, r, g, b}
__device__ int     g_start[N_RAYS];
__device__ int     g_end[N_RAYS];

// ---------------------------------------------------------------------------
// Kernel 1: transpose trivecs (P,C,3,DIM) fp32 -> (P,3,DIM,C) fp16.
// Two 4-p groups per 384-thread block. Folds in dens+colors fp16 pack and
// segment-table zeroing.
// ---------------------------------------------------------------------------
__global__ __launch_bounds__(384) void transpose_k(const float4* __restrict__ in,
                                                   const float4* __restrict__ densities4,
                                                   const float4* __restrict__ colors4) {
    __shared__ float sm[8 * PPAD];
    int t = threadIdx.x;
    int gid = blockIdx.x * 384 + t;            // up to 2.4M
    size_t base4 = (size_t)blockIdx.x * 768;   // float4 index of first 4-p group

    float4 v0 = __ldcs(in + base4 + t);
    float4 v1 = __ldcs(in + base4 + 384 + t);

    // folded init of segment tables
    if (gid < N_RAYS) { g_start[gid] = 0; g_end[gid] = 0; }
    // folded densities+colors fp32 -> fp16 pack: per-p block = 64 halves
    // [0:16) = densities, [16:64) = colors (c*3+k). Thread handles 4 floats.
    if (gid < P_CNT * 16) {
        int p = gid >> 4;
        int o = (gid & 15) * 4;                // 0,4,...,60
        float4 src = (o < 16)
            ? __ldcs(densities4 + ((size_t)p * 16 + o) / 4)
            : __ldcs(colors4    + ((size_t)p * 48 + (o - 16)) / 4);
        union { __half2 h[2]; uint2 u; } cv;
        cv.h[0] = __floats2half2_rn(src.x, src.y);
        cv.h[1] = __floats2half2_rn(src.z, src.w);
        reinterpret_cast<uint2*>(g_dc)[(size_t)p * 16 + (o >> 2)] = cv.u;
    }

    int m  = t * 4;                 // float offset within a 4-p group
    int pl = t / 96;                // local p (96 float4 per p)
    int mo = m - pl * PBLK;         // 0..383: row = mo/24 (c), col = mo%24 (a*8+d)
    int pi = mo + 2 * (mo / 24);    // padded index
    float* s0 = sm + pl * PPAD;
    float* s1 = sm + (4 + pl) * PPAD;
    s0[pi + 0] = v0.x; s0[pi + 1] = v0.y; s0[pi + 2] = v0.z; s0[pi + 3] = v0.w;
    s1[pi + 0] = v1.x; s1[pi + 1] = v1.y; s1[pi + 2] = v1.z; s1[pi + 3] = v1.w;
    __syncthreads();

    int c = mo & 15, d = (mo >> 4) & 7, a = mo >> 7;
    int i0 = c * 26 + a * 8 + d;
    const float* r0 = sm + pl * PPAD;
    const float* r1 = sm + (4 + pl) * PPAD;
    union { __half2 h[2]; uint2 u; } o0, o1;
    o0.h[0] = __floats2half2_rn(r0[i0],      r0[i0 + 26]);
    o0.h[1] = __floats2half2_rn(r0[i0 + 52], r0[i0 + 78]);
    o1.h[0] = __floats2half2_rn(r1[i0],      r1[i0 + 26]);
    o1.h[1] = __floats2half2_rn(r1[i0 + 52], r1[i0 + 78]);
    int oidx = pl * 96 + a * 32 + d * 4 + (c >> 2);
    uint2* outp = reinterpret_cast<uint2*>(g_trivecsH);
    outp[base4 + oidx]       = o0.u;
    outp[base4 + 384 + oidx] = o1.u;
}

// ---------------------------------------------------------------------------
// Kernel 2: per-sample feature/sigma/color (+ segment boundaries).
// 2 threads per sample, 8 channels each via 16B gathers; pair shuffle-reduce.
// ---------------------------------------------------------------------------
__global__ __launch_bounds__(256) void sample_k(
    const float* __restrict__ gws,         // (N, 3)
    const float* __restrict__ gwl,         // (N, 3)
    const int*   __restrict__ gis,         // (N, 3)
    const int*   __restrict__ gil,         // (N, 3)
    const int*   __restrict__ tfid,        // (N,)
    const int*   __restrict__ ray_id)      // (N,) sorted
{
    int t = blockIdx.x * blockDim.x + threadIdx.x;
    int n = t >> 1;
    if (n >= N_SAMPLES) return;
    int q = t & 1;
    int n3 = n * 3;

    int p = __ldcs(tfid + n);
    const __half* base = g_trivecsH + (size_t)p * PBLK + q * 8;

    float f[8];
    #pragma unroll
    for (int i = 0; i < 8; i++) f[i] = 1.f;

    #pragma unroll
    for (int a = 0; a < 3; a++) {
        int   is = __ldcs(gis + n3 + a);
        int   il = __ldcs(gil + n3 + a);
        float ws = __ldcs(gws + n3 + a);
        float wl = __ldcs(gwl + n3 + a);
        uint4 rs = *reinterpret_cast<const uint4*>(base + a * 128 + is * 16);
        uint4 rl = *reinterpret_cast<const uint4*>(base + a * 128 + il * 16);
        const __half2* hs = reinterpret_cast<const __half2*>(&rs);
        const __half2* hl = reinterpret_cast<const __half2*>(&rl);
        #pragma unroll
        for (int i = 0; i < 4; i++) {
            float2 vs = __half22float2(hs[i]);
            float2 vl = __half22float2(hl[i]);
            f[i * 2 + 0] *= vs.x * ws + vl.x * wl;
            f[i * 2 + 1] *= vs.y * ws + vl.y * wl;
        }
    }

    // densities: halves [q*8, q*8+8) of p's 64-half block
    const __half* dch = g_dc + (size_t)p * 64;
    uint4 du = *reinterpret_cast<const uint4*>(dch + q * 8);
    const __half2* dh = reinterpret_cast<const __half2*>(&du);
    float sig = 0.f;
    #pragma unroll
    for (int i = 0; i < 4; i++) {
        float2 dv = __half22float2(dh[i]);
        sig += f[i * 2 + 0] * dv.x + f[i * 2 + 1] * dv.y;
    }

    // colors: halves [16 + q*24, 16 + q*24 + 24); element (c_local,k) at c_local*3+k
    const __half* cbh = dch + 16 + q * 24;
    uint4 cu0 = *reinterpret_cast<const uint4*>(cbh);
    uint4 cu1 = *reinterpret_cast<const uint4*>(cbh + 8);
    uint4 cu2 = *reinterpret_cast<const uint4*>(cbh + 16);
    float col[24];
    {
        const __half2* ch = reinterpret_cast<const __half2*>(&cu0);
        #pragma unroll
        for (int i = 0; i < 4; i++) { float2 v = __half22float2(ch[i]); col[i*2] = v.x; col[i*2+1] = v.y; }
        ch = reinterpret_cast<const __half2*>(&cu1);
        #pragma unroll
        for (int i = 0; i < 4; i++) { float2 v = __half22float2(ch[i]); col[8+i*2] = v.x; col[8+i*2+1] = v.y; }
        ch = reinterpret_cast<const __half2*>(&cu2);
        #pragma unroll
        for (int i = 0; i < 4; i++) { float2 v = __half22float2(ch[i]); col[16+i*2] = v.x; col[16+i*2+1] = v.y; }
    }
    float cr = 0.f, cg = 0.f, cbv = 0.f;
    #pragma unroll
    for (int c = 0; c < 8; c++) {
        cr  += f[c] * col[c * 3 + 0];
        cg  += f[c] * col[c * 3 + 1];
        cbv += f[c] * col[c * 3 + 2];
    }

    // pair reduction
    sig += __shfl_xor_sync(0xffffffffu, sig, 1);
    cr  += __shfl_xor_sync(0xffffffffu, cr,  1);
    cg  += __shfl_xor_sync(0xffffffffu, cg,  1);
    cbv += __shfl_xor_sync(0xffffffffu, cbv, 1);

    if (q == 0) {
        // DENSITY_SHIFT = 0, DENSITY_SCALE = 1
        float density = (sig > 15.f) ? sig : log1pf(__expf(sig));
        float alpha = 1.f - __expf(-density * STEP_SIZE);
        float rr = 1.f / (1.f + __expf(-cr));
        float rg = 1.f / (1.f + __expf(-cg));
        float rb = 1.f / (1.f + __expf(-cbv));
        g_samp[n] = make_float4(alpha, rr, rg, rb);
    } else {
        // __ldg so the n-1/n/n+1 neighborhood hits L1
        int r = __ldg(ray_id + n);
        int rp = (n > 0) ? __ldg(ray_id + n - 1) : -1;
        int rn = (n < N_SAMPLES - 1) ? __ldg(ray_id + n + 1) : -1;
        if (rp != r) g_start[r] = n;
        if (rn != r) g_end[r]   = n + 1;
    }
}

// ---------------------------------------------------------------------------
// Kernel 3: thread-per-ray composite; multiplicative transmittance;
// depth-2 prefetch (two independent loads in flight).
// ---------------------------------------------------------------------------
__global__ __launch_bounds__(256) void ray_k(
    const int*   __restrict__ step_id,
    const float* __restrict__ t_min,
    const float* __restrict__ bg,
    float*       __restrict__ out)
{
    int r = blockIdx.x * blockDim.x + threadIdx.x;
    if (r >= N_RAYS) return;

    int s = g_start[r];
    int e = g_end[r];
    float tm = t_min[r];

    float T = 1.f;
    float ra = 0.f, ga = 0.f, ba = 0.f, da = 0.f;

    float4 sp0, sp1; int st0 = 0, st1 = 0;
    if (s < e)     { sp0 = __ldcs(g_samp + s);     st0 = __ldcs(step_id + s); }
    if (s + 1 < e) { sp1 = __ldcs(g_samp + s + 1); st1 = __ldcs(step_id + s + 1); }

    for (int j = s; j < e; j++) {
        float4 cur = sp0;
        int    cst = st0;
        sp0 = sp1; st0 = st1;
        if (j + 2 < e) { sp1 = __ldcs(g_samp + j + 2); st1 = __ldcs(step_id + j + 2); }
        float w = cur.x * T;
        ra += w * cur.y;
        ga += w * cur.z;
        ba += w * cur.w;
        da += w * (tm + (float)cst * STEP_SIZE);
        T *= (1.f - cur.x);
    }
    out[0 * N_RAYS + r] = ra + T * __ldg(bg + 0);
    out[1 * N_RAYS + r] = ga + T * __ldg(bg + 1);
    out[2 * N_RAYS + r] = ba + T * __ldg(bg + 2);
    out[3 * N_RAYS + r] = da;          // depth map
    out[4 * N_RAYS + r] = 1.f - T;     // alpha map
}

extern "C" void kernel_launch(void* const* d_in, const int* in_sizes, int n_in,
                              void* d_out, int out_size) {
    const float* trivecs   = (const float*)d_in[0];
    const float* densities = (const float*)d_in[1];
    const float* colors    = (const float*)d_in[2];
    const float* gws       = (const float*)d_in[3];
    const float* gwl       = (const float*)d_in[4];
    const float* t_min     = (const float*)d_in[5];
    const float* bg        = (const float*)d_in[6];
    const int*   gis       = (const int*)d_in[7];
    const int*   gil       = (const int*)d_in[8];
    const int*   tfid      = (const int*)d_in[9];
    const int*   ray_id    = (const int*)d_in[10];
    const int*   step_id   = (const int*)d_in[11];
    float* out = (float*)d_out;

    transpose_k<<<P_CNT / 8, 384>>>((const float4*)trivecs,
                                    (const float4*)densities,
                                    (const float4*)colors);
    sample_k<<<(2 * N_SAMPLES + 255) / 256, 256>>>(gws, gwl, gis, gil, tfid, ray_id);
    ray_k<<<(N_RAYS + 255) / 256, 256>>>(step_id, t_min, bg, out);
}